// round 12
// baseline (speedup 1.0000x reference)
#include <cuda_runtime.h>
#include <cuda_fp16.h>
#include <cstdint>
#include <math.h>

// ---------------------------------------------------------------------------
// Problem dims (fixed)
// ---------------------------------------------------------------------------
#define SEQ   1024
#define BATCH 16
#define HDIM  1024
#define KDIM  1024
#define MDIM  (SEQ * BATCH)     // 16384
#define NDIM  (3 * HDIM)        // 3072

// ---------------------------------------------------------------------------
// Device scratch (static only). Gates stored as fp16 (activated values).
// ---------------------------------------------------------------------------
__device__ __half g_Z[(size_t)MDIM * HDIM];
__device__ __half g_F[(size_t)MDIM * HDIM];
__device__ __half g_O[(size_t)MDIM * HDIM];

__device__ __half g_Xh[(size_t)MDIM * KDIM];
__device__ __half g_Wh[(size_t)NDIM * KDIM];

#define NCHUNK 64
#define CLEN   16               // SEQ / NCHUNK
#define NCHAIN (BATCH * HDIM)   // 16384
#define NC8    (NCHAIN / 8)     // 2048 chain-groups of 8
__device__ float g_cA[NCHUNK * NCHAIN];
__device__ float g_cB[NCHUNK * NCHAIN];
__device__ float g_cH[NCHUNK * NCHAIN];

// ---------------------------------------------------------------------------
// Helpers
// ---------------------------------------------------------------------------
static __device__ __forceinline__ uint32_t smem_u32(const void* p) {
    uint32_t a;
    asm("{ .reg .u64 t; cvta.to.shared.u64 t, %1; cvt.u32.u64 %0, t; }"
        : "=r"(a) : "l"(p));
    return a;
}

static __device__ __forceinline__ void cp16(uint32_t saddr, const void* gaddr) {
    asm volatile("cp.async.cg.shared.global [%0], [%1], 16;"
                 :: "r"(saddr), "l"(gaddr) : "memory");
}
#define CP_COMMIT() asm volatile("cp.async.commit_group;" ::: "memory")
#define CP_WAIT1()  asm volatile("cp.async.wait_group 1;" ::: "memory")

static __device__ __forceinline__ void ldsm4(uint32_t* r, uint32_t addr) {
    asm volatile("ldmatrix.sync.aligned.m8n8.x4.shared.b16 {%0,%1,%2,%3}, [%4];"
                 : "=r"(r[0]), "=r"(r[1]), "=r"(r[2]), "=r"(r[3]) : "r"(addr));
}

static __device__ __forceinline__ void mma16816(float* d, const uint32_t* a,
                                                const uint32_t* b) {
    asm volatile(
        "mma.sync.aligned.m16n8k16.row.col.f32.f16.f16.f32 "
        "{%0,%1,%2,%3}, {%4,%5,%6,%7}, {%8,%9}, {%0,%1,%2,%3};"
        : "+f"(d[0]), "+f"(d[1]), "+f"(d[2]), "+f"(d[3])
        : "r"(a[0]), "r"(a[1]), "r"(a[2]), "r"(a[3]), "r"(b[0]), "r"(b[1]));
}

static __device__ __forceinline__ float fast_sigmoid(float y) {
    return 1.0f / (1.0f + __expf(-y));
}
static __device__ __forceinline__ float fast_tanh(float y) {
    return 2.0f / (1.0f + __expf(-2.0f * y)) - 1.0f;
}

// ---------------------------------------------------------------------------
// fp32 -> fp16 conversion prepass
// ---------------------------------------------------------------------------
template <bool ISX>
__global__ __launch_bounds__(256) void conv_kernel(const float4* __restrict__ src) {
    int i = blockIdx.x * 256 + threadIdx.x;
    float4 v = src[i];
    __half2* dst = (__half2*)(ISX ? g_Xh : g_Wh);
    dst[2 * i + 0] = __floats2half2_rn(v.x, v.y);
    dst[2 * i + 1] = __floats2half2_rn(v.z, v.w);
}

// ---------------------------------------------------------------------------
// HMMA GEMM (R9 shape, software-pipelined B fragments): 128x128 tile, BK=64,
// 256 threads, 3-stage cp.async, 2 CTAs/SM, warp tiling 4m x 2n.
// Inside each kf: load A frags + B quad 0, then issue B quad nq+1's ldsm
// before the 4 MMAs consuming quad nq (hides ldsm latency in-warp).
// Y[m,n] = sum_k X[m,k]*W[n,k] + b[n]; fused bias+activation; fp16 gate store.
// smem rows are 64 fp16 = 128B; swizzle: 16B group g at row r -> g ^ (r&7).
// ---------------------------------------------------------------------------
#define BM 128
#define BN 128
#define BK 64
#define PLANE_BYTES (128 * 128)          // 16 KB
#define STAGE_BYTES (2 * PLANE_BYTES)    // 32 KB
#define NSTAGE 3
#define GEMM_SMEM (NSTAGE * STAGE_BYTES) // 96 KB -> 2 CTAs/SM
#define NCHK (KDIM / BK)                 // 16

#define OFF_A 0
#define OFF_B PLANE_BYTES

__global__ __launch_bounds__(256, 2) void gemm_hmma_kernel(
    const float* __restrict__ bias)
{
    extern __shared__ char sm[];
    const uint32_t sbase = smem_u32(sm);

    const int tid = threadIdx.x;
    const int wid = tid >> 5;
    const int lid = tid & 31;
    const int bm = blockIdx.y * BM;
    const int bn = blockIdx.x * BN;

    const int wm = wid >> 1;
    const int wn = wid & 1;

    float acc[2][8][4];
    #pragma unroll
    for (int i = 0; i < 2; i++)
        #pragma unroll
        for (int j = 0; j < 8; j++)
            #pragma unroll
            for (int q = 0; q < 4; q++)
                acc[i][j][q] = 0.0f;

    auto load_stage = [&](int c, int s) {
        const uint32_t sb = sbase + s * STAGE_BYTES;
        const int k0 = c * BK;
        #pragma unroll
        for (int i = 0; i < 4; i++) {
            const int u = tid + i * 256;          // 0..1023
            const int row = u >> 3;
            const int kg = u & 7;
            const uint32_t so = row * 128 + 16 * (kg ^ (row & 7));
            const size_t gx = ((size_t)(bm + row) * KDIM + k0 + kg * 8) * 2;
            const size_t gw = ((size_t)(bn + row) * KDIM + k0 + kg * 8) * 2;
            cp16(sb + OFF_A + so, (const char*)g_Xh + gx);
            cp16(sb + OFF_B + so, (const char*)g_Wh + gw);
        }
    };

    const int a_rl = lid & 15;
    const int a_kh = lid >> 4;
    const int b_rl = (lid & 7) + ((lid & 16) >> 1);
    const int b_kh = (lid >> 3) & 1;

    load_stage(0, 0); CP_COMMIT();
    load_stage(1, 1); CP_COMMIT();

    for (int c = 0; c < NCHK; c++) {
        CP_WAIT1();
        __syncthreads();
        if (c + 2 < NCHK) load_stage(c + 2, (c + 2) % NSTAGE);
        CP_COMMIT();

        const uint32_t sb = sbase + (c % NSTAGE) * STAGE_BYTES;

        #pragma unroll
        for (int kf = 0; kf < 4; kf++) {
            const int kga = 2 * kf + a_kh;
            const int kgb = 2 * kf + b_kh;

            uint32_t a[2][4];
            #pragma unroll
            for (int mf = 0; mf < 2; mf++) {
                const int row = wm * 32 + mf * 16 + a_rl;
                const uint32_t so = row * 128 + 16 * (kga ^ (row & 7));
                ldsm4(a[mf], sb + OFF_A + so);
            }

            // software-pipelined B quads: bq[cur] consumed while bq[nxt] loads
            uint32_t bq[2][4];
            {
                const int row = wn * 64 + 0 * 16 + b_rl;
                const uint32_t so = row * 128 + 16 * (kgb ^ (row & 7));
                ldsm4(bq[0], sb + OFF_B + so);
            }
            #pragma unroll
            for (int nq = 0; nq < 4; nq++) {
                if (nq < 3) {
                    const int row = wn * 64 + (nq + 1) * 16 + b_rl;
                    const uint32_t so = row * 128 + 16 * (kgb ^ (row & 7));
                    ldsm4(bq[(nq + 1) & 1], sb + OFF_B + so);
                }
                const uint32_t* t = bq[nq & 1];
                #pragma unroll
                for (int mf = 0; mf < 2; mf++) {
                    mma16816(acc[mf][nq * 2 + 0], a[mf], t + 0);
                    mma16816(acc[mf][nq * 2 + 1], a[mf], t + 2);
                }
            }
        }
    }

    // ---- epilogue: bias + activation, fp16 store to gate plane ----
    const int nch  = bn >> 10;                 // 0=Z(tanh), 1=F, 2=O (sigmoid)
    const int hoff = bn & 1023;
    __half* dst = (nch == 0) ? g_Z : (nch == 1) ? g_F : g_O;
    const float* bp = bias + bn + wn * 64;

    #pragma unroll
    for (int mf = 0; mf < 2; mf++) {
        const int r0 = bm + wm * 32 + mf * 16 + (lid >> 2);
        #pragma unroll
        for (int nf = 0; nf < 8; nf++) {
            const int col = nf * 8 + (lid & 3) * 2;
            const float b0 = __ldg(bp + col);
            const float b1 = __ldg(bp + col + 1);
            #pragma unroll
            for (int half = 0; half < 2; half++) {
                const int r = r0 + half * 8;
                float y0 = acc[mf][nf][2 * half + 0] + b0;
                float y1 = acc[mf][nf][2 * half + 1] + b1;
                float v0, v1;
                if (nch == 0) { v0 = fast_tanh(y0); v1 = fast_tanh(y1); }
                else          { v0 = fast_sigmoid(y0); v1 = fast_sigmoid(y1); }
                *(__half2*)&dst[(size_t)r * HDIM + hoff + wn * 64 + col] =
                    __floats2half2_rn(v0, v1);
            }
        }
    }
}

// ---------------------------------------------------------------------------
// Chunked scan over fp16 gates, 8 chains per thread (uint4 = 8 halves).
// h_t = f_t*z_t + (1-f_t)*h_{t-1}
// ---------------------------------------------------------------------------
static __device__ __forceinline__ void unpack8(const uint4& u, float* f) {
    const __half2* h = (const __half2*)&u;
    #pragma unroll
    for (int j = 0; j < 4; j++) {
        float2 p = __half22float2(h[j]);
        f[2 * j] = p.x; f[2 * j + 1] = p.y;
    }
}

__global__ __launch_bounds__(256) void scan_chunks_kernel() {
    const int c8 = blockIdx.x * 256 + threadIdx.x;   // 0..2047
    const int ck = blockIdx.y;
    const uint4* F8 = (const uint4*)g_F;
    const uint4* Z8 = (const uint4*)g_Z;
    size_t idx = (size_t)ck * CLEN * NC8 + c8;
    float A[8], Bv[8];
    #pragma unroll
    for (int j = 0; j < 8; j++) { A[j] = 1.0f; Bv[j] = 0.0f; }
    for (int s = 0; s < CLEN; s++, idx += NC8) {
        float f[8], z[8];
        unpack8(F8[idx], f);
        unpack8(Z8[idx], z);
        #pragma unroll
        for (int j = 0; j < 8; j++) {
            Bv[j] = fmaf(f[j], z[j] - Bv[j], Bv[j]);
            A[j] *= (1.0f - f[j]);
        }
    }
    float4* cA4 = (float4*)g_cA;
    float4* cB4 = (float4*)g_cB;
    const size_t o = (size_t)ck * (NC8 * 2) + c8 * 2;
    cA4[o + 0] = make_float4(A[0], A[1], A[2], A[3]);
    cA4[o + 1] = make_float4(A[4], A[5], A[6], A[7]);
    cB4[o + 0] = make_float4(Bv[0], Bv[1], Bv[2], Bv[3]);
    cB4[o + 1] = make_float4(Bv[4], Bv[5], Bv[6], Bv[7]);
}

__global__ __launch_bounds__(256) void scan_combine_kernel() {
    const int c8 = blockIdx.x * 256 + threadIdx.x;   // 0..2047
    float4 h0 = make_float4(0.f, 0.f, 0.f, 0.f);
    float4 h1 = make_float4(0.f, 0.f, 0.f, 0.f);
    const float4* cA4 = (const float4*)g_cA;
    const float4* cB4 = (const float4*)g_cB;
    float4* cH4 = (float4*)g_cH;
    #pragma unroll 8
    for (int c = 0; c < NCHUNK; c++) {
        const size_t o = (size_t)c * (NC8 * 2) + c8 * 2;
        cH4[o + 0] = h0;
        cH4[o + 1] = h1;
        const float4 A0 = cA4[o + 0], A1 = cA4[o + 1];
        const float4 B0 = cB4[o + 0], B1 = cB4[o + 1];
        h0.x = fmaf(A0.x, h0.x, B0.x); h0.y = fmaf(A0.y, h0.y, B0.y);
        h0.z = fmaf(A0.z, h0.z, B0.z); h0.w = fmaf(A0.w, h0.w, B0.w);
        h1.x = fmaf(A1.x, h1.x, B1.x); h1.y = fmaf(A1.y, h1.y, B1.y);
        h1.z = fmaf(A1.z, h1.z, B1.z); h1.w = fmaf(A1.w, h1.w, B1.w);
    }
}

__global__ __launch_bounds__(256) void scan_final_kernel(float* __restrict__ out) {
    const int c8 = blockIdx.x * 256 + threadIdx.x;   // 0..2047
    const int ck = blockIdx.y;
    const uint4* F8 = (const uint4*)g_F;
    const uint4* Z8 = (const uint4*)g_Z;
    const uint4* O8 = (const uint4*)g_O;
    float4* out4 = (float4*)out;
    size_t idx = (size_t)ck * CLEN * NC8 + c8;
    float h[8];
    {
        const float4* cH4 = (const float4*)g_cH;
        const size_t o = (size_t)ck * (NC8 * 2) + c8 * 2;
        float4 h0 = cH4[o + 0], h1 = cH4[o + 1];
        h[0]=h0.x; h[1]=h0.y; h[2]=h0.z; h[3]=h0.w;
        h[4]=h1.x; h[5]=h1.y; h[6]=h1.z; h[7]=h1.w;
    }
    for (int s = 0; s < CLEN; s++, idx += NC8) {
        float f[8], z[8], o[8];
        unpack8(F8[idx], f);
        unpack8(Z8[idx], z);
        unpack8(O8[idx], o);
        float r[8];
        #pragma unroll
        for (int j = 0; j < 8; j++) {
            h[j] = fmaf(f[j], z[j] - h[j], h[j]);
            r[j] = o[j] * h[j];
        }
        out4[idx * 2 + 0] = make_float4(r[0], r[1], r[2], r[3]);
        out4[idx * 2 + 1] = make_float4(r[4], r[5], r[6], r[7]);
    }
    if (ck == NCHUNK - 1) {
        const size_t o = (size_t)MDIM * HDIM / 4 + c8 * 2;
        out4[o + 0] = make_float4(h[0], h[1], h[2], h[3]);
        out4[o + 1] = make_float4(h[4], h[5], h[6], h[7]);
    }
}

// ---------------------------------------------------------------------------
extern "C" void kernel_launch(void* const* d_in, const int* in_sizes, int n_in,
                              void* d_out, int out_size) {
    const float* X    = (const float*)d_in[0];
    const float* W    = (const float*)d_in[1];
    const float* bias = (const float*)d_in[2];
    float* out = (float*)d_out;

    cudaFuncSetAttribute(gemm_hmma_kernel,
                         cudaFuncAttributeMaxDynamicSharedMemorySize, GEMM_SMEM);

    conv_kernel<true><<<(MDIM * KDIM / 4) / 256, 256>>>((const float4*)X);
    conv_kernel<false><<<(NDIM * KDIM / 4) / 256, 256>>>((const float4*)W);

    dim3 ggrid(NDIM / BN, MDIM / BM);   // (24, 128)
    gemm_hmma_kernel<<<ggrid, 256, GEMM_SMEM>>>(bias);

    dim3 sgrid(NC8 / 256, NCHUNK);      // (8, 64)
    scan_chunks_kernel<<<sgrid, 256>>>();
    scan_combine_kernel<<<NC8 / 256, 256>>>();
    scan_final_kernel<<<sgrid, 256>>>(out);
}

// round 13
// speedup vs baseline: 1.4897x; 1.4897x over previous
#include <cuda_runtime.h>
#include <cuda_fp16.h>
#include <cstdint>
#include <math.h>

// ---------------------------------------------------------------------------
// Problem dims (fixed)
// ---------------------------------------------------------------------------
#define SEQ   1024
#define BATCH 16
#define HDIM  1024
#define KDIM  1024
#define MDIM  (SEQ * BATCH)     // 16384
#define NDIM  (3 * HDIM)        // 3072

// ---------------------------------------------------------------------------
// Device scratch (static only). Gates stored as fp16 (activated values).
// ---------------------------------------------------------------------------
__device__ __half g_Z[(size_t)MDIM * HDIM];
__device__ __half g_F[(size_t)MDIM * HDIM];
__device__ __half g_O[(size_t)MDIM * HDIM];

__device__ __half g_Xh[(size_t)MDIM * KDIM];
__device__ __half g_Wh[(size_t)NDIM * KDIM];

#define NCHUNK 64
#define CLEN   16               // SEQ / NCHUNK
#define NCHAIN (BATCH * HDIM)   // 16384
#define NC8    (NCHAIN / 8)     // 2048 chain-groups of 8
__device__ float g_cA[NCHUNK * NCHAIN];
__device__ float g_cB[NCHUNK * NCHAIN];
__device__ float g_cH[NCHUNK * NCHAIN];

// ---------------------------------------------------------------------------
// Helpers
// ---------------------------------------------------------------------------
static __device__ __forceinline__ uint32_t smem_u32(const void* p) {
    uint32_t a;
    asm("{ .reg .u64 t; cvta.to.shared.u64 t, %1; cvt.u32.u64 %0, t; }"
        : "=r"(a) : "l"(p));
    return a;
}

static __device__ __forceinline__ void cp16(uint32_t saddr, const void* gaddr) {
    asm volatile("cp.async.cg.shared.global [%0], [%1], 16;"
                 :: "r"(saddr), "l"(gaddr) : "memory");
}
#define CP_COMMIT() asm volatile("cp.async.commit_group;" ::: "memory")
#define CP_WAIT1()  asm volatile("cp.async.wait_group 1;" ::: "memory")

static __device__ __forceinline__ void ldsm4(uint32_t* r, uint32_t addr) {
    asm volatile("ldmatrix.sync.aligned.m8n8.x4.shared.b16 {%0,%1,%2,%3}, [%4];"
                 : "=r"(r[0]), "=r"(r[1]), "=r"(r[2]), "=r"(r[3]) : "r"(addr));
}

static __device__ __forceinline__ void mma16816(float* d, const uint32_t* a,
                                                const uint32_t* b) {
    asm volatile(
        "mma.sync.aligned.m16n8k16.row.col.f32.f16.f16.f32 "
        "{%0,%1,%2,%3}, {%4,%5,%6,%7}, {%8,%9}, {%0,%1,%2,%3};"
        : "+f"(d[0]), "+f"(d[1]), "+f"(d[2]), "+f"(d[3])
        : "r"(a[0]), "r"(a[1]), "r"(a[2]), "r"(a[3]), "r"(b[0]), "r"(b[1]));
}

static __device__ __forceinline__ float fast_sigmoid(float y) {
    return 1.0f / (1.0f + __expf(-y));
}
static __device__ __forceinline__ float fast_tanh(float y) {
    return 2.0f / (1.0f + __expf(-2.0f * y)) - 1.0f;
}

// ---------------------------------------------------------------------------
// fp32 -> fp16 conversion prepass (X and W fused into one launch)
// ---------------------------------------------------------------------------
#define NX4 (MDIM * KDIM / 4)   // 4,194,304 float4 in X
#define NW4 (NDIM * KDIM / 4)   //   786,432 float4 in W

__global__ __launch_bounds__(256) void conv_kernel(
    const float4* __restrict__ X4, const float4* __restrict__ W4)
{
    const int i = blockIdx.x * 256 + threadIdx.x;
    const bool isx = i < NX4;
    const float4 v = isx ? X4[i] : W4[i - NX4];
    __half2* dst = isx ? (__half2*)g_Xh : (__half2*)g_Wh;
    const int j = isx ? i : (i - NX4);
    dst[2 * j + 0] = __floats2half2_rn(v.x, v.y);
    dst[2 * j + 1] = __floats2half2_rn(v.z, v.w);
}

// ---------------------------------------------------------------------------
// HMMA GEMM (R9 config, best measured: 362.6us total): 128x128 tile, BK=64,
// 256 threads, 3-stage cp.async, 2 CTAs/SM, warp tiling 4m x 2n.
// Y[m,n] = sum_k X[m,k]*W[n,k] + b[n]; fused bias+activation; fp16 gate store.
// smem rows are 64 fp16 = 128B; swizzle: 16B group g at row r -> g ^ (r&7).
// ---------------------------------------------------------------------------
#define BM 128
#define BN 128
#define BK 64
#define PLANE_BYTES (128 * 128)          // 16 KB
#define STAGE_BYTES (2 * PLANE_BYTES)    // 32 KB
#define NSTAGE 3
#define GEMM_SMEM (NSTAGE * STAGE_BYTES) // 96 KB -> 2 CTAs/SM
#define NCHK (KDIM / BK)                 // 16

#define OFF_A 0
#define OFF_B PLANE_BYTES

__global__ __launch_bounds__(256, 2) void gemm_hmma_kernel(
    const float* __restrict__ bias)
{
    extern __shared__ char sm[];
    const uint32_t sbase = smem_u32(sm);

    const int tid = threadIdx.x;
    const int wid = tid >> 5;
    const int lid = tid & 31;
    const int bm = blockIdx.y * BM;
    const int bn = blockIdx.x * BN;

    const int wm = wid >> 1;
    const int wn = wid & 1;

    float acc[2][8][4];
    #pragma unroll
    for (int i = 0; i < 2; i++)
        #pragma unroll
        for (int j = 0; j < 8; j++)
            #pragma unroll
            for (int q = 0; q < 4; q++)
                acc[i][j][q] = 0.0f;

    auto load_stage = [&](int c, int s) {
        const uint32_t sb = sbase + s * STAGE_BYTES;
        const int k0 = c * BK;
        #pragma unroll
        for (int i = 0; i < 4; i++) {
            const int u = tid + i * 256;          // 0..1023
            const int row = u >> 3;
            const int kg = u & 7;
            const uint32_t so = row * 128 + 16 * (kg ^ (row & 7));
            const size_t gx = ((size_t)(bm + row) * KDIM + k0 + kg * 8) * 2;
            const size_t gw = ((size_t)(bn + row) * KDIM + k0 + kg * 8) * 2;
            cp16(sb + OFF_A + so, (const char*)g_Xh + gx);
            cp16(sb + OFF_B + so, (const char*)g_Wh + gw);
        }
    };

    const int a_rl = lid & 15;
    const int a_kh = lid >> 4;
    const int b_rl = (lid & 7) + ((lid & 16) >> 1);
    const int b_kh = (lid >> 3) & 1;

    load_stage(0, 0); CP_COMMIT();
    load_stage(1, 1); CP_COMMIT();

    for (int c = 0; c < NCHK; c++) {
        CP_WAIT1();
        __syncthreads();
        if (c + 2 < NCHK) load_stage(c + 2, (c + 2) % NSTAGE);
        CP_COMMIT();

        const uint32_t sb = sbase + (c % NSTAGE) * STAGE_BYTES;

        #pragma unroll
        for (int kf = 0; kf < 4; kf++) {
            uint32_t a[2][4], b[8][2];

            #pragma unroll
            for (int mf = 0; mf < 2; mf++) {
                const int row = wm * 32 + mf * 16 + a_rl;
                const int kg = 2 * kf + a_kh;
                const uint32_t so = row * 128 + 16 * (kg ^ (row & 7));
                ldsm4(a[mf], sb + OFF_A + so);
            }
            #pragma unroll
            for (int nq = 0; nq < 4; nq++) {
                const int row = wn * 64 + nq * 16 + b_rl;
                const int kg = 2 * kf + b_kh;
                const uint32_t so = row * 128 + 16 * (kg ^ (row & 7));
                uint32_t t[4];
                ldsm4(t, sb + OFF_B + so);
                b[nq * 2][0] = t[0]; b[nq * 2][1] = t[1];
                b[nq * 2 + 1][0] = t[2]; b[nq * 2 + 1][1] = t[3];
            }

            #pragma unroll
            for (int mf = 0; mf < 2; mf++)
                #pragma unroll
                for (int nf = 0; nf < 8; nf++)
                    mma16816(acc[mf][nf], a[mf], b[nf]);
        }
    }

    // ---- epilogue: bias + activation, fp16 store to gate plane ----
    const int nch  = bn >> 10;                 // 0=Z(tanh), 1=F, 2=O (sigmoid)
    const int hoff = bn & 1023;
    __half* dst = (nch == 0) ? g_Z : (nch == 1) ? g_F : g_O;
    const float* bp = bias + bn + wn * 64;

    #pragma unroll
    for (int mf = 0; mf < 2; mf++) {
        const int r0 = bm + wm * 32 + mf * 16 + (lid >> 2);
        #pragma unroll
        for (int nf = 0; nf < 8; nf++) {
            const int col = nf * 8 + (lid & 3) * 2;
            const float b0 = __ldg(bp + col);
            const float b1 = __ldg(bp + col + 1);
            #pragma unroll
            for (int half = 0; half < 2; half++) {
                const int r = r0 + half * 8;
                float y0 = acc[mf][nf][2 * half + 0] + b0;
                float y1 = acc[mf][nf][2 * half + 1] + b1;
                float v0, v1;
                if (nch == 0) { v0 = fast_tanh(y0); v1 = fast_tanh(y1); }
                else          { v0 = fast_sigmoid(y0); v1 = fast_sigmoid(y1); }
                *(__half2*)&dst[(size_t)r * HDIM + hoff + wn * 64 + col] =
                    __floats2half2_rn(v0, v1);
            }
        }
    }
}

// ---------------------------------------------------------------------------
// Chunked scan over fp16 gates, 8 chains per thread (uint4 = 8 halves).
// h_t = f_t*z_t + (1-f_t)*h_{t-1}
// ---------------------------------------------------------------------------
static __device__ __forceinline__ void unpack8(const uint4& u, float* f) {
    const __half2* h = (const __half2*)&u;
    #pragma unroll
    for (int j = 0; j < 4; j++) {
        float2 p = __half22float2(h[j]);
        f[2 * j] = p.x; f[2 * j + 1] = p.y;
    }
}

__global__ __launch_bounds__(256) void scan_chunks_kernel() {
    const int c8 = blockIdx.x * 256 + threadIdx.x;   // 0..2047
    const int ck = blockIdx.y;
    const uint4* F8 = (const uint4*)g_F;
    const uint4* Z8 = (const uint4*)g_Z;
    size_t idx = (size_t)ck * CLEN * NC8 + c8;
    float A[8], Bv[8];
    #pragma unroll
    for (int j = 0; j < 8; j++) { A[j] = 1.0f; Bv[j] = 0.0f; }
    for (int s = 0; s < CLEN; s++, idx += NC8) {
        float f[8], z[8];
        unpack8(F8[idx], f);
        unpack8(Z8[idx], z);
        #pragma unroll
        for (int j = 0; j < 8; j++) {
            Bv[j] = fmaf(f[j], z[j] - Bv[j], Bv[j]);
            A[j] *= (1.0f - f[j]);
        }
    }
    float4* cA4 = (float4*)g_cA;
    float4* cB4 = (float4*)g_cB;
    const size_t o = (size_t)ck * (NC8 * 2) + c8 * 2;
    cA4[o + 0] = make_float4(A[0], A[1], A[2], A[3]);
    cA4[o + 1] = make_float4(A[4], A[5], A[6], A[7]);
    cB4[o + 0] = make_float4(Bv[0], Bv[1], Bv[2], Bv[3]);
    cB4[o + 1] = make_float4(Bv[4], Bv[5], Bv[6], Bv[7]);
}

__global__ __launch_bounds__(256) void scan_combine_kernel() {
    const int c8 = blockIdx.x * 256 + threadIdx.x;   // 0..2047
    float4 h0 = make_float4(0.f, 0.f, 0.f, 0.f);
    float4 h1 = make_float4(0.f, 0.f, 0.f, 0.f);
    const float4* cA4 = (const float4*)g_cA;
    const float4* cB4 = (const float4*)g_cB;
    float4* cH4 = (float4*)g_cH;
    #pragma unroll 8
    for (int c = 0; c < NCHUNK; c++) {
        const size_t o = (size_t)c * (NC8 * 2) + c8 * 2;
        cH4[o + 0] = h0;
        cH4[o + 1] = h1;
        const float4 A0 = cA4[o + 0], A1 = cA4[o + 1];
        const float4 B0 = cB4[o + 0], B1 = cB4[o + 1];
        h0.x = fmaf(A0.x, h0.x, B0.x); h0.y = fmaf(A0.y, h0.y, B0.y);
        h0.z = fmaf(A0.z, h0.z, B0.z); h0.w = fmaf(A0.w, h0.w, B0.w);
        h1.x = fmaf(A1.x, h1.x, B1.x); h1.y = fmaf(A1.y, h1.y, B1.y);
        h1.z = fmaf(A1.z, h1.z, B1.z); h1.w = fmaf(A1.w, h1.w, B1.w);
    }
}

__global__ __launch_bounds__(256) void scan_final_kernel(float* __restrict__ out) {
    const int c8 = blockIdx.x * 256 + threadIdx.x;   // 0..2047
    const int ck = blockIdx.y;
    const uint4* F8 = (const uint4*)g_F;
    const uint4* Z8 = (const uint4*)g_Z;
    const uint4* O8 = (const uint4*)g_O;
    float4* out4 = (float4*)out;
    size_t idx = (size_t)ck * CLEN * NC8 + c8;
    float h[8];
    {
        const float4* cH4 = (const float4*)g_cH;
        const size_t o = (size_t)ck * (NC8 * 2) + c8 * 2;
        float4 h0 = cH4[o + 0], h1 = cH4[o + 1];
        h[0]=h0.x; h[1]=h0.y; h[2]=h0.z; h[3]=h0.w;
        h[4]=h1.x; h[5]=h1.y; h[6]=h1.z; h[7]=h1.w;
    }
    for (int s = 0; s < CLEN; s++, idx += NC8) {
        float f[8], z[8], o[8];
        unpack8(F8[idx], f);
        unpack8(Z8[idx], z);
        unpack8(O8[idx], o);
        float r[8];
        #pragma unroll
        for (int j = 0; j < 8; j++) {
            h[j] = fmaf(f[j], z[j] - h[j], h[j]);
            r[j] = o[j] * h[j];
        }
        out4[idx * 2 + 0] = make_float4(r[0], r[1], r[2], r[3]);
        out4[idx * 2 + 1] = make_float4(r[4], r[5], r[6], r[7]);
    }
    if (ck == NCHUNK - 1) {
        const size_t o = (size_t)MDIM * HDIM / 4 + c8 * 2;
        out4[o + 0] = make_float4(h[0], h[1], h[2], h[3]);
        out4[o + 1] = make_float4(h[4], h[5], h[6], h[7]);
    }
}

// ---------------------------------------------------------------------------
extern "C" void kernel_launch(void* const* d_in, const int* in_sizes, int n_in,
                              void* d_out, int out_size) {
    const float* X    = (const float*)d_in[0];
    const float* W    = (const float*)d_in[1];
    const float* bias = (const float*)d_in[2];
    float* out = (float*)d_out;

    cudaFuncSetAttribute(gemm_hmma_kernel,
                         cudaFuncAttributeMaxDynamicSharedMemorySize, GEMM_SMEM);

    conv_kernel<<<(NX4 + NW4) / 256, 256>>>((const float4*)X, (const float4*)W);

    dim3 ggrid(NDIM / BN, MDIM / BM);   // (24, 128)
    gemm_hmma_kernel<<<ggrid, 256, GEMM_SMEM>>>(bias);

    dim3 sgrid(NC8 / 256, NCHUNK);      // (8, 64)
    scan_chunks_kernel<<<sgrid, 256>>>();
    scan_combine_kernel<<<NC8 / 256, 256>>>();
    scan_final_kernel<<<sgrid, 256>>>(out);
}

// round 14
// speedup vs baseline: 1.5047x; 1.0101x over previous
#include <cuda_runtime.h>
#include <cuda_fp16.h>
#include <cstdint>
#include <math.h>

// ---------------------------------------------------------------------------
// Problem dims (fixed)
// ---------------------------------------------------------------------------
#define SEQ   1024
#define BATCH 16
#define HDIM  1024
#define KDIM  1024
#define MDIM  (SEQ * BATCH)     // 16384
#define NDIM  (3 * HDIM)        // 3072

// ---------------------------------------------------------------------------
// Device scratch (static only). Gates stored as fp16 (activated values).
// ---------------------------------------------------------------------------
__device__ __half g_Z[(size_t)MDIM * HDIM];
__device__ __half g_F[(size_t)MDIM * HDIM];
__device__ __half g_O[(size_t)MDIM * HDIM];

__device__ __half g_Xh[(size_t)MDIM * KDIM];
__device__ __half g_Wh[(size_t)NDIM * KDIM];

#define NCHUNK 64
#define CLEN   16               // SEQ / NCHUNK
#define NCHAIN (BATCH * HDIM)   // 16384
#define NC8    (NCHAIN / 8)     // 2048 chain-groups of 8
__device__ float g_cA[NCHUNK * NCHAIN];
__device__ float g_cB[NCHUNK * NCHAIN];
__device__ float g_cH[NCHUNK * NCHAIN];

// ---------------------------------------------------------------------------
// Helpers
// ---------------------------------------------------------------------------
static __device__ __forceinline__ uint32_t smem_u32(const void* p) {
    uint32_t a;
    asm("{ .reg .u64 t; cvta.to.shared.u64 t, %1; cvt.u32.u64 %0, t; }"
        : "=r"(a) : "l"(p));
    return a;
}

static __device__ __forceinline__ void cp16(uint32_t saddr, const void* gaddr) {
    asm volatile("cp.async.cg.shared.global [%0], [%1], 16;"
                 :: "r"(saddr), "l"(gaddr) : "memory");
}
#define CP_COMMIT() asm volatile("cp.async.commit_group;" ::: "memory")
#define CP_WAIT1()  asm volatile("cp.async.wait_group 1;" ::: "memory")

static __device__ __forceinline__ void ldsm4(uint32_t* r, uint32_t addr) {
    asm volatile("ldmatrix.sync.aligned.m8n8.x4.shared.b16 {%0,%1,%2,%3}, [%4];"
                 : "=r"(r[0]), "=r"(r[1]), "=r"(r[2]), "=r"(r[3]) : "r"(addr));
}

static __device__ __forceinline__ void mma16816(float* d, const uint32_t* a,
                                                const uint32_t* b) {
    asm volatile(
        "mma.sync.aligned.m16n8k16.row.col.f32.f16.f16.f32 "
        "{%0,%1,%2,%3}, {%4,%5,%6,%7}, {%8,%9}, {%0,%1,%2,%3};"
        : "+f"(d[0]), "+f"(d[1]), "+f"(d[2]), "+f"(d[3])
        : "r"(a[0]), "r"(a[1]), "r"(a[2]), "r"(a[3]), "r"(b[0]), "r"(b[1]));
}

static __device__ __forceinline__ float fast_sigmoid(float y) {
    return 1.0f / (1.0f + __expf(-y));
}
static __device__ __forceinline__ float fast_tanh(float y) {
    return 2.0f / (1.0f + __expf(-2.0f * y)) - 1.0f;
}

// ---------------------------------------------------------------------------
// fp32 -> fp16 conversion prepass (X and W fused into one launch)
// ---------------------------------------------------------------------------
#define NX4 (MDIM * KDIM / 4)   // 4,194,304 float4 in X
#define NW4 (NDIM * KDIM / 4)   //   786,432 float4 in W

__global__ __launch_bounds__(256) void conv_kernel(
    const float4* __restrict__ X4, const float4* __restrict__ W4)
{
    const int i = blockIdx.x * 256 + threadIdx.x;
    const bool isx = i < NX4;
    const float4 v = isx ? X4[i] : W4[i - NX4];
    __half2* dst = isx ? (__half2*)g_Xh : (__half2*)g_Wh;
    const int j = isx ? i : (i - NX4);
    dst[2 * j + 0] = __floats2half2_rn(v.x, v.y);
    dst[2 * j + 1] = __floats2half2_rn(v.z, v.w);
}

// ---------------------------------------------------------------------------
// HMMA GEMM (R9 config, best measured): 128x128 tile, BK=64, 256 threads,
// 3-stage cp.async, 2 CTAs/SM, warp tiling 4m x 2n.
// Y[m,n] = sum_k X[m,k]*W[n,k] + b[n]; fused bias+activation; fp16 gate store.
// smem rows are 64 fp16 = 128B; swizzle: 16B group g at row r -> g ^ (r&7).
// ---------------------------------------------------------------------------
#define BM 128
#define BN 128
#define BK 64
#define PLANE_BYTES (128 * 128)          // 16 KB
#define STAGE_BYTES (2 * PLANE_BYTES)    // 32 KB
#define NSTAGE 3
#define GEMM_SMEM (NSTAGE * STAGE_BYTES) // 96 KB -> 2 CTAs/SM
#define NCHK (KDIM / BK)                 // 16

#define OFF_A 0
#define OFF_B PLANE_BYTES

__global__ __launch_bounds__(256, 2) void gemm_hmma_kernel(
    const float* __restrict__ bias)
{
    extern __shared__ char sm[];
    const uint32_t sbase = smem_u32(sm);

    const int tid = threadIdx.x;
    const int wid = tid >> 5;
    const int lid = tid & 31;
    const int bm = blockIdx.y * BM;
    const int bn = blockIdx.x * BN;

    const int wm = wid >> 1;
    const int wn = wid & 1;

    float acc[2][8][4];
    #pragma unroll
    for (int i = 0; i < 2; i++)
        #pragma unroll
        for (int j = 0; j < 8; j++)
            #pragma unroll
            for (int q = 0; q < 4; q++)
                acc[i][j][q] = 0.0f;

    auto load_stage = [&](int c, int s) {
        const uint32_t sb = sbase + s * STAGE_BYTES;
        const int k0 = c * BK;
        #pragma unroll
        for (int i = 0; i < 4; i++) {
            const int u = tid + i * 256;          // 0..1023
            const int row = u >> 3;
            const int kg = u & 7;
            const uint32_t so = row * 128 + 16 * (kg ^ (row & 7));
            const size_t gx = ((size_t)(bm + row) * KDIM + k0 + kg * 8) * 2;
            const size_t gw = ((size_t)(bn + row) * KDIM + k0 + kg * 8) * 2;
            cp16(sb + OFF_A + so, (const char*)g_Xh + gx);
            cp16(sb + OFF_B + so, (const char*)g_Wh + gw);
        }
    };

    const int a_rl = lid & 15;
    const int a_kh = lid >> 4;
    const int b_rl = (lid & 7) + ((lid & 16) >> 1);
    const int b_kh = (lid >> 3) & 1;

    load_stage(0, 0); CP_COMMIT();
    load_stage(1, 1); CP_COMMIT();

    for (int c = 0; c < NCHK; c++) {
        CP_WAIT1();
        __syncthreads();
        if (c + 2 < NCHK) load_stage(c + 2, (c + 2) % NSTAGE);
        CP_COMMIT();

        const uint32_t sb = sbase + (c % NSTAGE) * STAGE_BYTES;

        #pragma unroll
        for (int kf = 0; kf < 4; kf++) {
            uint32_t a[2][4], b[8][2];

            #pragma unroll
            for (int mf = 0; mf < 2; mf++) {
                const int row = wm * 32 + mf * 16 + a_rl;
                const int kg = 2 * kf + a_kh;
                const uint32_t so = row * 128 + 16 * (kg ^ (row & 7));
                ldsm4(a[mf], sb + OFF_A + so);
            }
            #pragma unroll
            for (int nq = 0; nq < 4; nq++) {
                const int row = wn * 64 + nq * 16 + b_rl;
                const int kg = 2 * kf + b_kh;
                const uint32_t so = row * 128 + 16 * (kg ^ (row & 7));
                uint32_t t[4];
                ldsm4(t, sb + OFF_B + so);
                b[nq * 2][0] = t[0]; b[nq * 2][1] = t[1];
                b[nq * 2 + 1][0] = t[2]; b[nq * 2 + 1][1] = t[3];
            }

            #pragma unroll
            for (int mf = 0; mf < 2; mf++)
                #pragma unroll
                for (int nf = 0; nf < 8; nf++)
                    mma16816(acc[mf][nf], a[mf], b[nf]);
        }
    }

    // ---- epilogue: bias + activation, fp16 store to gate plane ----
    const int nch  = bn >> 10;                 // 0=Z(tanh), 1=F, 2=O (sigmoid)
    const int hoff = bn & 1023;
    __half* dst = (nch == 0) ? g_Z : (nch == 1) ? g_F : g_O;
    const float* bp = bias + bn + wn * 64;

    #pragma unroll
    for (int mf = 0; mf < 2; mf++) {
        const int r0 = bm + wm * 32 + mf * 16 + (lid >> 2);
        #pragma unroll
        for (int nf = 0; nf < 8; nf++) {
            const int col = nf * 8 + (lid & 3) * 2;
            const float b0 = __ldg(bp + col);
            const float b1 = __ldg(bp + col + 1);
            #pragma unroll
            for (int half = 0; half < 2; half++) {
                const int r = r0 + half * 8;
                float y0 = acc[mf][nf][2 * half + 0] + b0;
                float y1 = acc[mf][nf][2 * half + 1] + b1;
                float v0, v1;
                if (nch == 0) { v0 = fast_tanh(y0); v1 = fast_tanh(y1); }
                else          { v0 = fast_sigmoid(y0); v1 = fast_sigmoid(y1); }
                *(__half2*)&dst[(size_t)r * HDIM + hoff + wn * 64 + col] =
                    __floats2half2_rn(v0, v1);
            }
        }
    }
}

// ---------------------------------------------------------------------------
// Chunked scan over fp16 gates, 8 chains per thread (uint4 = 8 halves).
// h_t = f_t*z_t + (1-f_t)*h_{t-1}
// ---------------------------------------------------------------------------
static __device__ __forceinline__ void unpack8(const uint4& u, float* f) {
    const __half2* h = (const __half2*)&u;
    #pragma unroll
    for (int j = 0; j < 4; j++) {
        float2 p = __half22float2(h[j]);
        f[2 * j] = p.x; f[2 * j + 1] = p.y;
    }
}

__global__ __launch_bounds__(256) void scan_chunks_kernel() {
    const int c8 = blockIdx.x * 256 + threadIdx.x;   // 0..2047
    const int ck = blockIdx.y;
    const uint4* F8 = (const uint4*)g_F;
    const uint4* Z8 = (const uint4*)g_Z;
    size_t idx = (size_t)ck * CLEN * NC8 + c8;
    float A[8], Bv[8];
    #pragma unroll
    for (int j = 0; j < 8; j++) { A[j] = 1.0f; Bv[j] = 0.0f; }
    for (int s = 0; s < CLEN; s++, idx += NC8) {
        float f[8], z[8];
        unpack8(F8[idx], f);
        unpack8(Z8[idx], z);
        #pragma unroll
        for (int j = 0; j < 8; j++) {
            Bv[j] = fmaf(f[j], z[j] - Bv[j], Bv[j]);
            A[j] *= (1.0f - f[j]);
        }
    }
    float4* cA4 = (float4*)g_cA;
    float4* cB4 = (float4*)g_cB;
    const size_t o = (size_t)ck * (NC8 * 2) + c8 * 2;
    cA4[o + 0] = make_float4(A[0], A[1], A[2], A[3]);
    cA4[o + 1] = make_float4(A[4], A[5], A[6], A[7]);
    cB4[o + 0] = make_float4(Bv[0], Bv[1], Bv[2], Bv[3]);
    cB4[o + 1] = make_float4(Bv[4], Bv[5], Bv[6], Bv[7]);
}

// One scalar chain per thread: 16384 threads = 64 blocks. Coalesced walks of
// cA/cB/cH (layout [chunk][chain], identical float indexing to the float4
// producers/consumers). Loads are independent of the h-chain -> unroll 16
// gives ~16 loads in flight per thread to amortize DRAM latency.
__global__ __launch_bounds__(256) void scan_combine_kernel() {
    const int chain = blockIdx.x * 256 + threadIdx.x;   // 0..16383
    float h = 0.0f;
    #pragma unroll 16
    for (int c = 0; c < NCHUNK; c++) {
        const size_t o = (size_t)c * NCHAIN + chain;
        g_cH[o] = h;
        h = fmaf(g_cA[o], h, g_cB[o]);
    }
}

__global__ __launch_bounds__(256) void scan_final_kernel(float* __restrict__ out) {
    const int c8 = blockIdx.x * 256 + threadIdx.x;   // 0..2047
    const int ck = blockIdx.y;
    const uint4* F8 = (const uint4*)g_F;
    const uint4* Z8 = (const uint4*)g_Z;
    const uint4* O8 = (const uint4*)g_O;
    float4* out4 = (float4*)out;
    size_t idx = (size_t)ck * CLEN * NC8 + c8;
    float h[8];
    {
        const float4* cH4 = (const float4*)g_cH;
        const size_t o = (size_t)ck * (NC8 * 2) + c8 * 2;
        float4 h0 = cH4[o + 0], h1 = cH4[o + 1];
        h[0]=h0.x; h[1]=h0.y; h[2]=h0.z; h[3]=h0.w;
        h[4]=h1.x; h[5]=h1.y; h[6]=h1.z; h[7]=h1.w;
    }
    for (int s = 0; s < CLEN; s++, idx += NC8) {
        float f[8], z[8], o[8];
        unpack8(F8[idx], f);
        unpack8(Z8[idx], z);
        unpack8(O8[idx], o);
        float r[8];
        #pragma unroll
        for (int j = 0; j < 8; j++) {
            h[j] = fmaf(f[j], z[j] - h[j], h[j]);
            r[j] = o[j] * h[j];
        }
        out4[idx * 2 + 0] = make_float4(r[0], r[1], r[2], r[3]);
        out4[idx * 2 + 1] = make_float4(r[4], r[5], r[6], r[7]);
    }
    if (ck == NCHUNK - 1) {
        const size_t o = (size_t)MDIM * HDIM / 4 + c8 * 2;
        out4[o + 0] = make_float4(h[0], h[1], h[2], h[3]);
        out4[o + 1] = make_float4(h[4], h[5], h[6], h[7]);
    }
}

// ---------------------------------------------------------------------------
extern "C" void kernel_launch(void* const* d_in, const int* in_sizes, int n_in,
                              void* d_out, int out_size) {
    const float* X    = (const float*)d_in[0];
    const float* W    = (const float*)d_in[1];
    const float* bias = (const float*)d_in[2];
    float* out = (float*)d_out;

    cudaFuncSetAttribute(gemm_hmma_kernel,
                         cudaFuncAttributeMaxDynamicSharedMemorySize, GEMM_SMEM);

    conv_kernel<<<(NX4 + NW4) / 256, 256>>>((const float4*)X, (const float4*)W);

    dim3 ggrid(NDIM / BN, MDIM / BM);   // (24, 128)
    gemm_hmma_kernel<<<ggrid, 256, GEMM_SMEM>>>(bias);

    dim3 sgrid(NC8 / 256, NCHUNK);      // (8, 64)
    scan_chunks_kernel<<<sgrid, 256>>>();
    scan_combine_kernel<<<NCHAIN / 256, 256>>>();
    scan_final_kernel<<<sgrid, 256>>>(out);
}

// round 15
// speedup vs baseline: 1.5598x; 1.0366x over previous
#include <cuda_runtime.h>
#include <cuda_fp16.h>
#include <cstdint>
#include <math.h>

// ---------------------------------------------------------------------------
// Problem dims (fixed)
// ---------------------------------------------------------------------------
#define SEQ   1024
#define BATCH 16
#define HDIM  1024
#define KDIM  1024
#define MDIM  (SEQ * BATCH)     // 16384
#define NDIM  (3 * HDIM)        // 3072

// ---------------------------------------------------------------------------
// Device scratch (static only). Gates stored as fp16 (activated values).
// ---------------------------------------------------------------------------
__device__ __half g_Z[(size_t)MDIM * HDIM];
__device__ __half g_F[(size_t)MDIM * HDIM];
__device__ __half g_O[(size_t)MDIM * HDIM];

__device__ __half g_Xh[(size_t)MDIM * KDIM];
__device__ __half g_Wh[(size_t)NDIM * KDIM];

#define NCHUNK 64
#define CLEN   16               // SEQ / NCHUNK
#define NCHAIN (BATCH * HDIM)   // 16384
#define NC8    (NCHAIN / 8)     // 2048 chain-groups of 8
__device__ float g_cA[NCHUNK * NCHAIN];
__device__ float g_cB[NCHUNK * NCHAIN];
__device__ float g_cH[NCHUNK * NCHAIN];

// ---------------------------------------------------------------------------
// Helpers
// ---------------------------------------------------------------------------
static __device__ __forceinline__ uint32_t smem_u32(const void* p) {
    uint32_t a;
    asm("{ .reg .u64 t; cvta.to.shared.u64 t, %1; cvt.u32.u64 %0, t; }"
        : "=r"(a) : "l"(p));
    return a;
}

static __device__ __forceinline__ void cp16(uint32_t saddr, const void* gaddr) {
    asm volatile("cp.async.cg.shared.global [%0], [%1], 16;"
                 :: "r"(saddr), "l"(gaddr) : "memory");
}
#define CP_COMMIT() asm volatile("cp.async.commit_group;" ::: "memory")
#define CP_WAIT1()  asm volatile("cp.async.wait_group 1;" ::: "memory")

static __device__ __forceinline__ void ldsm4(uint32_t* r, uint32_t addr) {
    asm volatile("ldmatrix.sync.aligned.m8n8.x4.shared.b16 {%0,%1,%2,%3}, [%4];"
                 : "=r"(r[0]), "=r"(r[1]), "=r"(r[2]), "=r"(r[3]) : "r"(addr));
}

static __device__ __forceinline__ void mma16816(float* d, const uint32_t* a,
                                                const uint32_t* b) {
    asm volatile(
        "mma.sync.aligned.m16n8k16.row.col.f32.f16.f16.f32 "
        "{%0,%1,%2,%3}, {%4,%5,%6,%7}, {%8,%9}, {%0,%1,%2,%3};"
        : "+f"(d[0]), "+f"(d[1]), "+f"(d[2]), "+f"(d[3])
        : "r"(a[0]), "r"(a[1]), "r"(a[2]), "r"(a[3]), "r"(b[0]), "r"(b[1]));
}

static __device__ __forceinline__ float fast_sigmoid(float y) {
    return 1.0f / (1.0f + __expf(-y));
}
static __device__ __forceinline__ float fast_tanh(float y) {
    return 2.0f / (1.0f + __expf(-2.0f * y)) - 1.0f;
}

// ---------------------------------------------------------------------------
// fp32 -> fp16 conversion prepass (X and W fused into one launch)
// ---------------------------------------------------------------------------
#define NX4 (MDIM * KDIM / 4)   // 4,194,304 float4 in X
#define NW4 (NDIM * KDIM / 4)   //   786,432 float4 in W

__global__ __launch_bounds__(256) void conv_kernel(
    const float4* __restrict__ X4, const float4* __restrict__ W4)
{
    const int i = blockIdx.x * 256 + threadIdx.x;
    const bool isx = i < NX4;
    const float4 v = isx ? X4[i] : W4[i - NX4];
    __half2* dst = isx ? (__half2*)g_Xh : (__half2*)g_Wh;
    const int j = isx ? i : (i - NX4);
    dst[2 * j + 0] = __floats2half2_rn(v.x, v.y);
    dst[2 * j + 1] = __floats2half2_rn(v.z, v.w);
}

// ---------------------------------------------------------------------------
// HMMA GEMM (R9 config, best measured): 128x128 tile, BK=64, 256 threads,
// 3-stage cp.async, 2 CTAs/SM, warp tiling 4m x 2n.
// Y[m,n] = sum_k X[m,k]*W[n,k] + b[n]; fused bias+activation; fp16 gate store.
// smem rows are 64 fp16 = 128B; swizzle: 16B group g at row r -> g ^ (r&7).
// ---------------------------------------------------------------------------
#define BM 128
#define BN 128
#define BK 64
#define PLANE_BYTES (128 * 128)          // 16 KB
#define STAGE_BYTES (2 * PLANE_BYTES)    // 32 KB
#define NSTAGE 3
#define GEMM_SMEM (NSTAGE * STAGE_BYTES) // 96 KB -> 2 CTAs/SM
#define NCHK (KDIM / BK)                 // 16

#define OFF_A 0
#define OFF_B PLANE_BYTES

__global__ __launch_bounds__(256, 2) void gemm_hmma_kernel(
    const float* __restrict__ bias)
{
    extern __shared__ char sm[];
    const uint32_t sbase = smem_u32(sm);

    const int tid = threadIdx.x;
    const int wid = tid >> 5;
    const int lid = tid & 31;
    const int bm = blockIdx.y * BM;
    const int bn = blockIdx.x * BN;

    const int wm = wid >> 1;
    const int wn = wid & 1;

    float acc[2][8][4];
    #pragma unroll
    for (int i = 0; i < 2; i++)
        #pragma unroll
        for (int j = 0; j < 8; j++)
            #pragma unroll
            for (int q = 0; q < 4; q++)
                acc[i][j][q] = 0.0f;

    auto load_stage = [&](int c, int s) {
        const uint32_t sb = sbase + s * STAGE_BYTES;
        const int k0 = c * BK;
        #pragma unroll
        for (int i = 0; i < 4; i++) {
            const int u = tid + i * 256;          // 0..1023
            const int row = u >> 3;
            const int kg = u & 7;
            const uint32_t so = row * 128 + 16 * (kg ^ (row & 7));
            const size_t gx = ((size_t)(bm + row) * KDIM + k0 + kg * 8) * 2;
            const size_t gw = ((size_t)(bn + row) * KDIM + k0 + kg * 8) * 2;
            cp16(sb + OFF_A + so, (const char*)g_Xh + gx);
            cp16(sb + OFF_B + so, (const char*)g_Wh + gw);
        }
    };

    const int a_rl = lid & 15;
    const int a_kh = lid >> 4;
    const int b_rl = (lid & 7) + ((lid & 16) >> 1);
    const int b_kh = (lid >> 3) & 1;

    load_stage(0, 0); CP_COMMIT();
    load_stage(1, 1); CP_COMMIT();

    for (int c = 0; c < NCHK; c++) {
        CP_WAIT1();
        __syncthreads();
        if (c + 2 < NCHK) load_stage(c + 2, (c + 2) % NSTAGE);
        CP_COMMIT();

        const uint32_t sb = sbase + (c % NSTAGE) * STAGE_BYTES;

        #pragma unroll
        for (int kf = 0; kf < 4; kf++) {
            uint32_t a[2][4], b[8][2];

            #pragma unroll
            for (int mf = 0; mf < 2; mf++) {
                const int row = wm * 32 + mf * 16 + a_rl;
                const int kg = 2 * kf + a_kh;
                const uint32_t so = row * 128 + 16 * (kg ^ (row & 7));
                ldsm4(a[mf], sb + OFF_A + so);
            }
            #pragma unroll
            for (int nq = 0; nq < 4; nq++) {
                const int row = wn * 64 + nq * 16 + b_rl;
                const int kg = 2 * kf + b_kh;
                const uint32_t so = row * 128 + 16 * (kg ^ (row & 7));
                uint32_t t[4];
                ldsm4(t, sb + OFF_B + so);
                b[nq * 2][0] = t[0]; b[nq * 2][1] = t[1];
                b[nq * 2 + 1][0] = t[2]; b[nq * 2 + 1][1] = t[3];
            }

            #pragma unroll
            for (int mf = 0; mf < 2; mf++)
                #pragma unroll
                for (int nf = 0; nf < 8; nf++)
                    mma16816(acc[mf][nf], a[mf], b[nf]);
        }
    }

    // ---- epilogue: bias + activation, fp16 store to gate plane ----
    const int nch  = bn >> 10;                 // 0=Z(tanh), 1=F, 2=O (sigmoid)
    const int hoff = bn & 1023;
    __half* dst = (nch == 0) ? g_Z : (nch == 1) ? g_F : g_O;
    const float* bp = bias + bn + wn * 64;

    #pragma unroll
    for (int mf = 0; mf < 2; mf++) {
        const int r0 = bm + wm * 32 + mf * 16 + (lid >> 2);
        #pragma unroll
        for (int nf = 0; nf < 8; nf++) {
            const int col = nf * 8 + (lid & 3) * 2;
            const float b0 = __ldg(bp + col);
            const float b1 = __ldg(bp + col + 1);
            #pragma unroll
            for (int half = 0; half < 2; half++) {
                const int r = r0 + half * 8;
                float y0 = acc[mf][nf][2 * half + 0] + b0;
                float y1 = acc[mf][nf][2 * half + 1] + b1;
                float v0, v1;
                if (nch == 0) { v0 = fast_tanh(y0); v1 = fast_tanh(y1); }
                else          { v0 = fast_sigmoid(y0); v1 = fast_sigmoid(y1); }
                *(__half2*)&dst[(size_t)r * HDIM + hoff + wn * 64 + col] =
                    __floats2half2_rn(v0, v1);
            }
        }
    }
}

// ---------------------------------------------------------------------------
// Chunked scan over fp16 gates, 8 chains per thread (uint4 = 8 halves).
// h_t = f_t*z_t + (1-f_t)*h_{t-1}
// ---------------------------------------------------------------------------
static __device__ __forceinline__ void unpack8(const uint4& u, float* f) {
    const __half2* h = (const __half2*)&u;
    #pragma unroll
    for (int j = 0; j < 4; j++) {
        float2 p = __half22float2(h[j]);
        f[2 * j] = p.x; f[2 * j + 1] = p.y;
    }
}

__global__ __launch_bounds__(256) void scan_chunks_kernel() {
    const int c8 = blockIdx.x * 256 + threadIdx.x;   // 0..2047
    const int ck = blockIdx.y;
    const uint4* F8 = (const uint4*)g_F;
    const uint4* Z8 = (const uint4*)g_Z;
    size_t idx = (size_t)ck * CLEN * NC8 + c8;
    float A[8], Bv[8];
    #pragma unroll
    for (int j = 0; j < 8; j++) { A[j] = 1.0f; Bv[j] = 0.0f; }
    for (int s = 0; s < CLEN; s++, idx += NC8) {
        float f[8], z[8];
        unpack8(F8[idx], f);
        unpack8(Z8[idx], z);
        #pragma unroll
        for (int j = 0; j < 8; j++) {
            Bv[j] = fmaf(f[j], z[j] - Bv[j], Bv[j]);
            A[j] *= (1.0f - f[j]);
        }
    }
    float4* cA4 = (float4*)g_cA;
    float4* cB4 = (float4*)g_cB;
    const size_t o = (size_t)ck * (NC8 * 2) + c8 * 2;
    cA4[o + 0] = make_float4(A[0], A[1], A[2], A[3]);
    cA4[o + 1] = make_float4(A[4], A[5], A[6], A[7]);
    cB4[o + 0] = make_float4(Bv[0], Bv[1], Bv[2], Bv[3]);
    cB4[o + 1] = make_float4(Bv[4], Bv[5], Bv[6], Bv[7]);
}

// One scalar chain per thread, batches of 8 with explicit register staging:
// the 16 loads of a batch are consumed by the following compute loop, so
// ptxas MUST issue them all before the first fma -> 16 loads in flight.
__global__ __launch_bounds__(256) void scan_combine_kernel() {
    const int chain = blockIdx.x * 256 + threadIdx.x;   // 0..16383
    float h = 0.0f;
    for (int cb = 0; cb < NCHUNK; cb += 8) {
        float As[8], Bs[8];
        #pragma unroll
        for (int j = 0; j < 8; j++) {
            const size_t o = (size_t)(cb + j) * NCHAIN + chain;
            As[j] = g_cA[o];
            Bs[j] = g_cB[o];
        }
        #pragma unroll
        for (int j = 0; j < 8; j++) {
            g_cH[(size_t)(cb + j) * NCHAIN + chain] = h;
            h = fmaf(As[j], h, Bs[j]);
        }
    }
}

__global__ __launch_bounds__(256) void scan_final_kernel(float* __restrict__ out) {
    const int c8 = blockIdx.x * 256 + threadIdx.x;   // 0..2047
    const int ck = blockIdx.y;
    const uint4* F8 = (const uint4*)g_F;
    const uint4* Z8 = (const uint4*)g_Z;
    const uint4* O8 = (const uint4*)g_O;
    float4* out4 = (float4*)out;
    size_t idx = (size_t)ck * CLEN * NC8 + c8;
    float h[8];
    {
        const float4* cH4 = (const float4*)g_cH;
        const size_t o = (size_t)ck * (NC8 * 2) + c8 * 2;
        float4 h0 = cH4[o + 0], h1 = cH4[o + 1];
        h[0]=h0.x; h[1]=h0.y; h[2]=h0.z; h[3]=h0.w;
        h[4]=h1.x; h[5]=h1.y; h[6]=h1.z; h[7]=h1.w;
    }
    for (int s = 0; s < CLEN; s++, idx += NC8) {
        float f[8], z[8], o[8];
        unpack8(F8[idx], f);
        unpack8(Z8[idx], z);
        unpack8(O8[idx], o);
        float r[8];
        #pragma unroll
        for (int j = 0; j < 8; j++) {
            h[j] = fmaf(f[j], z[j] - h[j], h[j]);
            r[j] = o[j] * h[j];
        }
        out4[idx * 2 + 0] = make_float4(r[0], r[1], r[2], r[3]);
        out4[idx * 2 + 1] = make_float4(r[4], r[5], r[6], r[7]);
    }
    if (ck == NCHUNK - 1) {
        const size_t o = (size_t)MDIM * HDIM / 4 + c8 * 2;
        out4[o + 0] = make_float4(h[0], h[1], h[2], h[3]);
        out4[o + 1] = make_float4(h[4], h[5], h[6], h[7]);
    }
}

// ---------------------------------------------------------------------------
extern "C" void kernel_launch(void* const* d_in, const int* in_sizes, int n_in,
                              void* d_out, int out_size) {
    const float* X    = (const float*)d_in[0];
    const float* W    = (const float*)d_in[1];
    const float* bias = (const float*)d_in[2];
    float* out = (float*)d_out;

    cudaFuncSetAttribute(gemm_hmma_kernel,
                         cudaFuncAttributeMaxDynamicSharedMemorySize, GEMM_SMEM);

    conv_kernel<<<(NX4 + NW4) / 256, 256>>>((const float4*)X, (const float4*)W);

    dim3 ggrid(NDIM / BN, MDIM / BM);   // (24, 128)
    gemm_hmma_kernel<<<ggrid, 256, GEMM_SMEM>>>(bias);

    dim3 sgrid(NC8 / 256, NCHUNK);      // (8, 64)
    scan_chunks_kernel<<<sgrid, 256>>>();
    scan_combine_kernel<<<NCHAIN / 256, 256>>>();
    scan_final_kernel<<<sgrid, 256>>>(out);
}

// round 16
// speedup vs baseline: 1.5875x; 1.0178x over previous
#include <cuda_runtime.h>
#include <cuda_fp16.h>
#include <cstdint>
#include <math.h>

// ---------------------------------------------------------------------------
// Problem dims (fixed)
// ---------------------------------------------------------------------------
#define SEQ   1024
#define BATCH 16
#define HDIM  1024
#define KDIM  1024
#define MDIM  (SEQ * BATCH)     // 16384
#define NDIM  (3 * HDIM)        // 3072

// ---------------------------------------------------------------------------
// Device scratch (static only). Gates stored as fp16 (activated values).
// ---------------------------------------------------------------------------
__device__ __half g_Z[(size_t)MDIM * HDIM];
__device__ __half g_F[(size_t)MDIM * HDIM];
__device__ __half g_O[(size_t)MDIM * HDIM];

__device__ __half g_Xh[(size_t)MDIM * KDIM];
__device__ __half g_Wh[(size_t)NDIM * KDIM];

#define NCHUNK 64
#define CLEN   16               // SEQ / NCHUNK
#define NCHAIN (BATCH * HDIM)   // 16384
#define NCG4   (NCHAIN / 4)     // 4096 chain-groups of 4
__device__ float g_cA[NCHUNK * NCHAIN];
__device__ float g_cB[NCHUNK * NCHAIN];
__device__ float g_cH[NCHUNK * NCHAIN];

// ---------------------------------------------------------------------------
// Helpers
// ---------------------------------------------------------------------------
static __device__ __forceinline__ uint32_t smem_u32(const void* p) {
    uint32_t a;
    asm("{ .reg .u64 t; cvta.to.shared.u64 t, %1; cvt.u32.u64 %0, t; }"
        : "=r"(a) : "l"(p));
    return a;
}

static __device__ __forceinline__ void cp16(uint32_t saddr, const void* gaddr) {
    asm volatile("cp.async.cg.shared.global [%0], [%1], 16;"
                 :: "r"(saddr), "l"(gaddr) : "memory");
}
#define CP_COMMIT() asm volatile("cp.async.commit_group;" ::: "memory")
#define CP_WAIT1()  asm volatile("cp.async.wait_group 1;" ::: "memory")

static __device__ __forceinline__ void ldsm4(uint32_t* r, uint32_t addr) {
    asm volatile("ldmatrix.sync.aligned.m8n8.x4.shared.b16 {%0,%1,%2,%3}, [%4];"
                 : "=r"(r[0]), "=r"(r[1]), "=r"(r[2]), "=r"(r[3]) : "r"(addr));
}

static __device__ __forceinline__ void mma16816(float* d, const uint32_t* a,
                                                const uint32_t* b) {
    asm volatile(
        "mma.sync.aligned.m16n8k16.row.col.f32.f16.f16.f32 "
        "{%0,%1,%2,%3}, {%4,%5,%6,%7}, {%8,%9}, {%0,%1,%2,%3};"
        : "+f"(d[0]), "+f"(d[1]), "+f"(d[2]), "+f"(d[3])
        : "r"(a[0]), "r"(a[1]), "r"(a[2]), "r"(a[3]), "r"(b[0]), "r"(b[1]));
}

static __device__ __forceinline__ float fast_sigmoid(float y) {
    return 1.0f / (1.0f + __expf(-y));
}
static __device__ __forceinline__ float fast_tanh(float y) {
    return 2.0f / (1.0f + __expf(-2.0f * y)) - 1.0f;
}

// ---------------------------------------------------------------------------
// fp32 -> fp16 conversion prepass (X and W fused into one launch)
// ---------------------------------------------------------------------------
#define NX4 (MDIM * KDIM / 4)   // 4,194,304 float4 in X
#define NW4 (NDIM * KDIM / 4)   //   786,432 float4 in W

__global__ __launch_bounds__(256) void conv_kernel(
    const float4* __restrict__ X4, const float4* __restrict__ W4)
{
    const int i = blockIdx.x * 256 + threadIdx.x;
    const bool isx = i < NX4;
    const float4 v = isx ? X4[i] : W4[i - NX4];
    __half2* dst = isx ? (__half2*)g_Xh : (__half2*)g_Wh;
    const int j = isx ? i : (i - NX4);
    dst[2 * j + 0] = __floats2half2_rn(v.x, v.y);
    dst[2 * j + 1] = __floats2half2_rn(v.z, v.w);
}

// ---------------------------------------------------------------------------
// HMMA GEMM (R9 config, best measured): 128x128 tile, BK=64, 256 threads,
// 3-stage cp.async, 2 CTAs/SM, warp tiling 4m x 2n.
// Y[m,n] = sum_k X[m,k]*W[n,k] + b[n]; fused bias+activation; fp16 gate store.
// smem rows are 64 fp16 = 128B; swizzle: 16B group g at row r -> g ^ (r&7).
// ---------------------------------------------------------------------------
#define BM 128
#define BN 128
#define BK 64
#define PLANE_BYTES (128 * 128)          // 16 KB
#define STAGE_BYTES (2 * PLANE_BYTES)    // 32 KB
#define NSTAGE 3
#define GEMM_SMEM (NSTAGE * STAGE_BYTES) // 96 KB -> 2 CTAs/SM
#define NCHK (KDIM / BK)                 // 16

#define OFF_A 0
#define OFF_B PLANE_BYTES

__global__ __launch_bounds__(256, 2) void gemm_hmma_kernel(
    const float* __restrict__ bias)
{
    extern __shared__ char sm[];
    const uint32_t sbase = smem_u32(sm);

    const int tid = threadIdx.x;
    const int wid = tid >> 5;
    const int lid = tid & 31;
    const int bm = blockIdx.y * BM;
    const int bn = blockIdx.x * BN;

    const int wm = wid >> 1;
    const int wn = wid & 1;

    float acc[2][8][4];
    #pragma unroll
    for (int i = 0; i < 2; i++)
        #pragma unroll
        for (int j = 0; j < 8; j++)
            #pragma unroll
            for (int q = 0; q < 4; q++)
                acc[i][j][q] = 0.0f;

    auto load_stage = [&](int c, int s) {
        const uint32_t sb = sbase + s * STAGE_BYTES;
        const int k0 = c * BK;
        #pragma unroll
        for (int i = 0; i < 4; i++) {
            const int u = tid + i * 256;          // 0..1023
            const int row = u >> 3;
            const int kg = u & 7;
            const uint32_t so = row * 128 + 16 * (kg ^ (row & 7));
            const size_t gx = ((size_t)(bm + row) * KDIM + k0 + kg * 8) * 2;
            const size_t gw = ((size_t)(bn + row) * KDIM + k0 + kg * 8) * 2;
            cp16(sb + OFF_A + so, (const char*)g_Xh + gx);
            cp16(sb + OFF_B + so, (const char*)g_Wh + gw);
        }
    };

    const int a_rl = lid & 15;
    const int a_kh = lid >> 4;
    const int b_rl = (lid & 7) + ((lid & 16) >> 1);
    const int b_kh = (lid >> 3) & 1;

    load_stage(0, 0); CP_COMMIT();
    load_stage(1, 1); CP_COMMIT();

    for (int c = 0; c < NCHK; c++) {
        CP_WAIT1();
        __syncthreads();
        if (c + 2 < NCHK) load_stage(c + 2, (c + 2) % NSTAGE);
        CP_COMMIT();

        const uint32_t sb = sbase + (c % NSTAGE) * STAGE_BYTES;

        #pragma unroll
        for (int kf = 0; kf < 4; kf++) {
            uint32_t a[2][4], b[8][2];

            #pragma unroll
            for (int mf = 0; mf < 2; mf++) {
                const int row = wm * 32 + mf * 16 + a_rl;
                const int kg = 2 * kf + a_kh;
                const uint32_t so = row * 128 + 16 * (kg ^ (row & 7));
                ldsm4(a[mf], sb + OFF_A + so);
            }
            #pragma unroll
            for (int nq = 0; nq < 4; nq++) {
                const int row = wn * 64 + nq * 16 + b_rl;
                const int kg = 2 * kf + b_kh;
                const uint32_t so = row * 128 + 16 * (kg ^ (row & 7));
                uint32_t t[4];
                ldsm4(t, sb + OFF_B + so);
                b[nq * 2][0] = t[0]; b[nq * 2][1] = t[1];
                b[nq * 2 + 1][0] = t[2]; b[nq * 2 + 1][1] = t[3];
            }

            #pragma unroll
            for (int mf = 0; mf < 2; mf++)
                #pragma unroll
                for (int nf = 0; nf < 8; nf++)
                    mma16816(acc[mf][nf], a[mf], b[nf]);
        }
    }

    // ---- epilogue: bias + activation, fp16 store to gate plane ----
    const int nch  = bn >> 10;                 // 0=Z(tanh), 1=F, 2=O (sigmoid)
    const int hoff = bn & 1023;
    __half* dst = (nch == 0) ? g_Z : (nch == 1) ? g_F : g_O;
    const float* bp = bias + bn + wn * 64;

    #pragma unroll
    for (int mf = 0; mf < 2; mf++) {
        const int r0 = bm + wm * 32 + mf * 16 + (lid >> 2);
        #pragma unroll
        for (int nf = 0; nf < 8; nf++) {
            const int col = nf * 8 + (lid & 3) * 2;
            const float b0 = __ldg(bp + col);
            const float b1 = __ldg(bp + col + 1);
            #pragma unroll
            for (int half = 0; half < 2; half++) {
                const int r = r0 + half * 8;
                float y0 = acc[mf][nf][2 * half + 0] + b0;
                float y1 = acc[mf][nf][2 * half + 1] + b1;
                float v0, v1;
                if (nch == 0) { v0 = fast_tanh(y0); v1 = fast_tanh(y1); }
                else          { v0 = fast_sigmoid(y0); v1 = fast_sigmoid(y1); }
                *(__half2*)&dst[(size_t)r * HDIM + hoff + wn * 64 + col] =
                    __floats2half2_rn(v0, v1);
            }
        }
    }
}

// ---------------------------------------------------------------------------
// Chunked scan over fp16 gates, 4 chains per thread (uint2 = 4 halves),
// 1024-block grids for DRAM occupancy.
// h_t = f_t*z_t + (1-f_t)*h_{t-1}
// ---------------------------------------------------------------------------
static __device__ __forceinline__ void unpack4(const uint2& u, float* f) {
    const __half2* h = (const __half2*)&u;
    float2 p0 = __half22float2(h[0]);
    float2 p1 = __half22float2(h[1]);
    f[0] = p0.x; f[1] = p0.y; f[2] = p1.x; f[3] = p1.y;
}

__global__ __launch_bounds__(256) void scan_chunks_kernel() {
    const int cg = blockIdx.x * 256 + threadIdx.x;   // 0..4095
    const int ck = blockIdx.y;
    const uint2* F4 = (const uint2*)g_F;
    const uint2* Z4 = (const uint2*)g_Z;
    size_t idx = (size_t)ck * CLEN * NCG4 + cg;
    float A[4], Bv[4];
    #pragma unroll
    for (int j = 0; j < 4; j++) { A[j] = 1.0f; Bv[j] = 0.0f; }
    #pragma unroll 4
    for (int s = 0; s < CLEN; s++, idx += NCG4) {
        float f[4], z[4];
        unpack4(F4[idx], f);
        unpack4(Z4[idx], z);
        #pragma unroll
        for (int j = 0; j < 4; j++) {
            Bv[j] = fmaf(f[j], z[j] - Bv[j], Bv[j]);
            A[j] *= (1.0f - f[j]);
        }
    }
    const size_t o = (size_t)ck * NCG4 + cg;
    ((float4*)g_cA)[o] = make_float4(A[0], A[1], A[2], A[3]);
    ((float4*)g_cB)[o] = make_float4(Bv[0], Bv[1], Bv[2], Bv[3]);
}

// One scalar chain per thread, batches of 16 with explicit register staging
// (32 independent loads in flight per thread); 128-thread blocks -> 128 blocks.
__global__ __launch_bounds__(128) void scan_combine_kernel() {
    const int chain = blockIdx.x * 128 + threadIdx.x;   // 0..16383
    float h = 0.0f;
    for (int cb = 0; cb < NCHUNK; cb += 16) {
        float As[16], Bs[16];
        #pragma unroll
        for (int j = 0; j < 16; j++) {
            const size_t o = (size_t)(cb + j) * NCHAIN + chain;
            As[j] = g_cA[o];
            Bs[j] = g_cB[o];
        }
        #pragma unroll
        for (int j = 0; j < 16; j++) {
            g_cH[(size_t)(cb + j) * NCHAIN + chain] = h;
            h = fmaf(As[j], h, Bs[j]);
        }
    }
}

__global__ __launch_bounds__(256) void scan_final_kernel(float* __restrict__ out) {
    const int cg = blockIdx.x * 256 + threadIdx.x;   // 0..4095
    const int ck = blockIdx.y;
    const uint2* F4 = (const uint2*)g_F;
    const uint2* Z4 = (const uint2*)g_Z;
    const uint2* O4 = (const uint2*)g_O;
    float4* out4 = (float4*)out;
    size_t idx = (size_t)ck * CLEN * NCG4 + cg;
    float h[4];
    {
        const float4 h0 = ((const float4*)g_cH)[(size_t)ck * NCG4 + cg];
        h[0] = h0.x; h[1] = h0.y; h[2] = h0.z; h[3] = h0.w;
    }
    #pragma unroll 4
    for (int s = 0; s < CLEN; s++, idx += NCG4) {
        float f[4], z[4], o[4];
        unpack4(F4[idx], f);
        unpack4(Z4[idx], z);
        unpack4(O4[idx], o);
        float r[4];
        #pragma unroll
        for (int j = 0; j < 4; j++) {
            h[j] = fmaf(f[j], z[j] - h[j], h[j]);
            r[j] = o[j] * h[j];
        }
        out4[idx] = make_float4(r[0], r[1], r[2], r[3]);
    }
    if (ck == NCHUNK - 1)
        out4[(size_t)MDIM * HDIM / 4 + cg] = make_float4(h[0], h[1], h[2], h[3]);
}

// ---------------------------------------------------------------------------
extern "C" void kernel_launch(void* const* d_in, const int* in_sizes, int n_in,
                              void* d_out, int out_size) {
    const float* X    = (const float*)d_in[0];
    const float* W    = (const float*)d_in[1];
    const float* bias = (const float*)d_in[2];
    float* out = (float*)d_out;

    cudaFuncSetAttribute(gemm_hmma_kernel,
                         cudaFuncAttributeMaxDynamicSharedMemorySize, GEMM_SMEM);

    conv_kernel<<<(NX4 + NW4) / 256, 256>>>((const float4*)X, (const float4*)W);

    dim3 ggrid(NDIM / BN, MDIM / BM);   // (24, 128)
    gemm_hmma_kernel<<<ggrid, 256, GEMM_SMEM>>>(bias);

    dim3 sgrid(NCG4 / 256, NCHUNK);     // (16, 64)
    scan_chunks_kernel<<<sgrid, 256>>>();
    scan_combine_kernel<<<NCHAIN / 128, 128>>>();
    scan_final_kernel<<<sgrid, 256>>>(out);
}